// round 9
// baseline (speedup 1.0000x reference)
#include <cuda_runtime.h>
#include <stdint.h>

#define T_STEPS 2000
#define BATCH   1024
#define NS      16
#define NA      4
#define STRIDE_T (BATCH * NS)

#define C_CHUNKS 10
#define K_CHUNK  200     // payload timesteps per chunk (C*K = T)
#define HALO     48      // 6 groups of 8: 4 PFC-only + 2 full warm-up

// per-(batch,chunk,action) payload PMC spike counts; every slot written each run
__device__ int g_part[BATCH * C_CHUNKS * NA];
__device__ int g_done = 0;   // block completion counter; reset by the finalizer

__global__ __launch_bounds__(64, 9)
void bg_kernel(const float* __restrict__ pfc,
               const float* __restrict__ w_pfc_d1,
               const float* __restrict__ w_pfc_d2,
               float* __restrict__ out, int out_size)
{
    __shared__ float2 lutA[256][NA];
    __shared__ float2 lutB[256][NA];
    __shared__ int s_last;

    const int tid = threadIdx.x;
    for (int e = tid; e < 512; e += blockDim.x) {
        const int hi = e >> 8;
        const int m  = e & 255;
        const int ibase = hi ? 8 : 0;
        #pragma unroll
        for (int jj = 0; jj < NA; jj++) {
            float a1 = 0.0f, a2 = 0.0f;
            #pragma unroll
            for (int i = 0; i < 8; i++)
                if ((m >> i) & 1) {
                    a1 += w_pfc_d1[(ibase + i) * NA + jj];
                    a2 += w_pfc_d2[(ibase + i) * NA + jj];
                }
            if (hi) lutB[m][jj] = make_float2(a1, a2);
            else    lutA[m][jj] = make_float2(a1, a2);
        }
    }
    __syncthreads();

    const int lane  = tid & 31;
    const int w     = blockIdx.x * 2 + (tid >> 5);  // global warp 0..2559
    const int quad  = w / C_CHUNKS;                 // batch quad 0..255
    const int chunk = w - quad * C_CHUNKS;          // 0..9
    const int grp   = lane >> 3;                    // batch-within-warp 0..3
    const int pos   = lane & 7;                     // neuron index (also pos+8)
    const int b     = quad * 4 + grp;
    const int j     = pos & 3;
    const unsigned full = 0xffffffffu;
    const unsigned sel = 0x4440u | (unsigned)grp;   // extract byte grp, zero-extend

    // pathway weights, exact reference fp32 op order
    const float w1j = (j == 0) ? 0.2f : (j == 1) ? 0.12f : (j == 2) ? 0.07f : 0.03f;
    const float w2j = (j == 0) ? 0.03f : (j == 1) ? 0.07f : (j == 2) ? 0.12f : 0.2f;
    const float W_D1_GPI   = (-1.0f * w1j) * 5.0f;
    const float W_D2_GPE   = (-1.0f * w1j) * 5.0f;
    const float W_GPE_STN  = (-0.8f * w1j) * 5.0f;
    const float W_STN_GPI  = (1.2f  * w1j) * 5.0f;
    const float W_GPI_THAL = (-1.0f * w2j) * 5.0f;
    const float W_THAL_PMC = (1.0f  * w1j) * 5.0f;

    // GPE..PMC exactly stateless => s_pmc = f(s_d1, s_d2); 4-entry truth table
    // built with one exact LIF step per layer from v=0 (v' = x exactly).
    int tt = 0;
    #pragma unroll
    for (int cb = 0; cb < 4; cb++) {
        float sd1 = (cb & 2) ? 1.0f : 0.0f;
        float sd2 = (cb & 1) ? 1.0f : 0.0f;
        float xg = sd2 * W_D2_GPE + 1.5f;
        float sg = (xg >= 1.0f) ? 1.0f : 0.0f;
        float xs = sg * W_GPE_STN + 1.8f;
        float ss = (xs >= 1.0f) ? 1.0f : 0.0f;
        float xi = (sd1 * W_D1_GPI + ss * W_STN_GPI) + 1.5f;
        float si = (xi >= 1.0f) ? 1.0f : 0.0f;
        float xt = si * W_GPI_THAL + 1.2f;
        float st = (xt >= 1.0f) ? 1.0f : 0.0f;
        float xp = st * W_THAL_PMC + 0.5f;
        if (xp >= 1.0f) tt |= 1 << cb;
    }
    const int c00 = tt & 1, c01 = (tt >> 1) & 1, c10 = (tt >> 2) & 1, c11 = (tt >> 3) & 1;

    // chunk geometry: ngroups groups of 8 steps; both cases ngroups % 3 == 1
    const int t0      = chunk * K_CHUNK - (chunk ? HALO : 0);
    const int ngroups = chunk ? 31 : 25;
    const int nT      = chunk ? 10 : 8;   // triples; leftover group = ngroups-1
    const int P       = chunk ? 4 : 0;    // first P groups: PFC-only warm-up
    const int ZG      = chunk ? 6 : 0;    // zero acc before B of (group ZG, k==1)

    float v0 = 0.0f, v1 = 0.0f, vd1 = 0.0f, vd2 = 0.0f;
    int acc = 0;
    unsigned m_lo = 0, m_hi = 0;   // skew registers: ballots of the previous step

    // stage B: consume previous step's masks -> LUT -> d1/d2 LIF -> count
    #define STAGE_B()                                                      \
    {                                                                      \
        unsigned mlo = __byte_perm(m_lo, 0u, sel);                         \
        unsigned mhi = __byte_perm(m_hi, 0u, sel);                         \
        float2 A  = lutA[mlo][j];                                          \
        float2 Bv = lutB[mhi][j];                                          \
        float d1c = A.x + Bv.x;                                            \
        float d2c = A.y + Bv.y;                                            \
        float e1 = d1c - vd1; vd1 = vd1 + e1;                              \
        bool p1 = (vd1 >= 1.0f); vd1 = p1 ? 0.0f : vd1;                    \
        float e2 = d2c - vd2; vd2 = vd2 + e2;                              \
        bool p2 = (vd2 >= 1.0f); vd2 = p2 ? 0.0f : vd2;                    \
        acc += p1 ? (p2 ? c11 : c10) : (p2 ? c01 : c00);                   \
    }

    // stage A: two PFC neurons + ballots (produce this step's masks)
    #define STAGE_A(xa, xb)                                                \
    {                                                                      \
        float dv0 = (xa) - v0; v0 = v0 + dv0;                              \
        bool f0 = (v0 >= 1.0f); v0 = f0 ? 0.0f : v0;                       \
        float dv1 = (xb) - v1; v1 = v1 + dv1;                              \
        bool f1 = (v1 >= 1.0f); v1 = f1 ? 0.0f : v1;                       \
        m_lo = __ballot_sync(full, f0);                                    \
        m_hi = __ballot_sync(full, f1);                                    \
    }

    // PFC-only halo step (no ballot, no B; downstream state renews later)
    #define STEP_PFC(xa, xb)                                               \
    {                                                                      \
        float dv0 = (xa) - v0; v0 = v0 + dv0;                              \
        if (v0 >= 1.0f) v0 = 0.0f;                                         \
        float dv1 = (xb) - v1; v1 = v1 + dv1;                              \
        if (v1 >= 1.0f) v1 = 0.0f;                                         \
    }

    // process one 8-step group from buffer slot s, runtime group index gi
    #define GROUP(s, gi)                                                   \
    {                                                                      \
        if ((gi) < P) {                                                    \
            _Pragma("unroll")                                              \
            for (int k = 0; k < 8; k++) STEP_PFC(xa##s[k], xb##s[k]);      \
        } else {                                                           \
            _Pragma("unroll")                                              \
            for (int k = 0; k < 8; k++) {                                  \
                if (k == 1 && (gi) == ZG) acc = 0;                         \
                STAGE_B();                                                 \
                STAGE_A(xa##s[k], xb##s[k]);                               \
            }                                                              \
        }                                                                  \
    }

    const float* p0    = pfc + (size_t)t0 * STRIDE_T + b * NS + pos;
    const float* psafe = pfc + b * NS + pos;   // clamp target for OOB prefetch

    // load group g into buffer slot s (clamped past chunk end; data unused)
    #define LOADG(s, g)                                                    \
    {                                                                      \
        const float* q = ((g) < ngroups)                                   \
            ? p0 + (size_t)(g) * (8 * STRIDE_T) : psafe;                   \
        _Pragma("unroll")                                                  \
        for (int k = 0; k < 8; k++) {                                      \
            xa##s[k] = q[k * STRIDE_T];                                    \
            xb##s[k] = q[k * STRIDE_T + 8];                                \
        }                                                                  \
    }

    float xa0[8], xb0[8], xa1[8], xb1[8], xa2[8], xb2[8];

    LOADG(0, 0);
    LOADG(1, 1);
    LOADG(2, 2);

    // triple-buffered main loop: ~2-group (~16-step) prefetch distance
    #pragma unroll 1
    for (int i = 0; i < nT; i++) {
        const int g3 = 3 * i;
        GROUP(0, g3);
        LOADG(0, g3 + 3);
        GROUP(1, g3 + 1);
        LOADG(1, g3 + 4);
        GROUP(2, g3 + 2);
        LOADG(2, g3 + 5);
    }
    GROUP(0, 3 * nT);   // leftover group (ngroups-1), already in slot 0

    STAGE_B();          // drain: count the final step

    #undef LOADG
    #undef GROUP
    #undef STEP_PFC
    #undef STAGE_A
    #undef STAGE_B

    if (pos < 4) g_part[(b * C_CHUNKS + chunk) * NA + j] = acc;

    // ---- last-block fused finalize ----
    __syncthreads();
    if (tid == 0) {
        __threadfence();
        int old = atomicAdd(&g_done, 1);
        s_last = (old == (int)gridDim.x - 1) ? 1 : 0;
    }
    __syncthreads();
    if (s_last) {
        __threadfence();   // acquire: all blocks' g_part writes visible
        for (int bb = tid; bb < BATCH; bb += 64) {
            int c0 = 0, c1 = 0, c2 = 0, c3 = 0;
            #pragma unroll
            for (int ch = 0; ch < C_CHUNKS; ch++) {
                const int4 v4 = *(const int4*)&g_part[(bb * C_CHUNKS + ch) * NA];
                c0 += v4.x; c1 += v4.y; c2 += v4.z; c3 += v4.w;
            }
            int best = 0, bv = c0;
            if (c1 > bv) { bv = c1; best = 1; }
            if (c2 > bv) { bv = c2; best = 2; }
            if (c3 > bv) { bv = c3; best = 3; }

            if (out_size == BATCH * (1 + NA)) {
                out[bb] = (float)best;
                out[BATCH + bb * NA + 0] = (float)c0;
                out[BATCH + bb * NA + 1] = (float)c1;
                out[BATCH + bb * NA + 2] = (float)c2;
                out[BATCH + bb * NA + 3] = (float)c3;
            } else if (out_size == BATCH * NA) {
                out[bb * NA + 0] = (float)c0;
                out[bb * NA + 1] = (float)c1;
                out[bb * NA + 2] = (float)c2;
                out[bb * NA + 3] = (float)c3;
            } else if (out_size == BATCH) {
                ((int*)out)[bb] = best;
            } else {
                if (bb * NA + 3 < out_size) {
                    out[bb * NA + 0] = (float)c0;
                    out[bb * NA + 1] = (float)c1;
                    out[bb * NA + 2] = (float)c2;
                    out[bb * NA + 3] = (float)c3;
                }
                if (BATCH * NA + bb < out_size) out[BATCH * NA + bb] = (float)best;
            }
        }
        if (tid == 0) g_done = 0;   // reset for next graph replay
    }
}

extern "C" void kernel_launch(void* const* d_in, const int* in_sizes, int n_in,
                              void* d_out, int out_size) {
    const float* pfc = (const float*)d_in[0];   // [2000, 1024, 16] f32
    const float* w1  = (const float*)d_in[1];   // [16, 4] f32
    const float* w2  = (const float*)d_in[2];   // [16, 4] f32

    // 256 batch-quads x 10 chunks = 2560 warps -> 1280 blocks of 2 warps
    // (64-thread blocks: 1280/148 = 8.65 -> 9 vs 8 blocks/SM, ~4% imbalance
    //  instead of 5 vs 4 with 128-thread blocks)
    bg_kernel<<<1280, 64>>>(pfc, w1, w2, (float*)d_out, out_size);
}